// round 1
// baseline (speedup 1.0000x reference)
#include <cuda_runtime.h>
#include <math.h>

// NT-Xent loss, N=4096, D=256, T=0.5, EPS=1e-8.
// loss = (S_d - 2N*S_p) / (2N)^2
//   S_p = sum_j positives[j]/T            (each of the 4096 pair-dots appears twice)
//   S_d = sum_j [(2N-1)*log(rs_j) + log(max(rs_j - 1, EPS))]
//   rs_j = sum_k exp(sim[j][k]/T),  sim = zn @ zn^T, zn = row-normalized concat(z_i,z_j)

#define NROWS 8192
#define NHALF 4096
#define DDIM  256
// exp(s/T) = exp(2s) = 2^(s * 2*log2(e))
#define LOG2E_X2 2.8853900817779268f

__device__ float g_zn[NROWS * DDIM];   // normalized reps (fp32)
__device__ float g_rs[NROWS];          // row sums of exp(sim/T)
__device__ float g_sum_p;              // S_p accumulator

// ---------------------------------------------------------------------------
// Kernel 1: row-normalize concat(z_i, z_j); also zero accumulators (graph-safe)
// 1024 blocks x 256 threads; one warp per row.
// ---------------------------------------------------------------------------
__global__ void __launch_bounds__(256) k_normalize(const float* __restrict__ zi,
                                                   const float* __restrict__ zj) {
    int gtid = blockIdx.x * 256 + threadIdx.x;
    if (gtid < NROWS) g_rs[gtid] = 0.0f;
    if (gtid == 0)    g_sum_p = 0.0f;

    int row  = gtid >> 5;
    int lane = threadIdx.x & 31;
    if (row >= NROWS) return;

    const float* src = (row < NHALF) ? (zi + (size_t)row * DDIM)
                                     : (zj + (size_t)(row - NHALF) * DDIM);
    float4 v0 = ((const float4*)src)[lane];
    float4 v1 = ((const float4*)src)[lane + 32];
    float s = v0.x*v0.x + v0.y*v0.y + v0.z*v0.z + v0.w*v0.w
            + v1.x*v1.x + v1.y*v1.y + v1.z*v1.z + v1.w*v1.w;
    #pragma unroll
    for (int o = 16; o > 0; o >>= 1) s += __shfl_xor_sync(0xffffffffu, s, o);

    float inv = 1.0f / fmaxf(sqrtf(s), 1e-8f);
    float4 w0 = make_float4(v0.x*inv, v0.y*inv, v0.z*inv, v0.w*inv);
    float4 w1 = make_float4(v1.x*inv, v1.y*inv, v1.z*inv, v1.w*inv);
    float4* dst = (float4*)(g_zn + (size_t)row * DDIM);
    dst[lane]      = w0;
    dst[lane + 32] = w1;
}

// ---------------------------------------------------------------------------
// Kernel 2: S_p = sum_j positives[j]/T = (2/T) * sum_{i<N} dot(zn[i], zn[i+N])
// 512 blocks x 256 threads; one warp per pair i.
// ---------------------------------------------------------------------------
__global__ void __launch_bounds__(256) k_positives() {
    int gtid = blockIdx.x * 256 + threadIdx.x;
    int i    = gtid >> 5;
    int lane = threadIdx.x & 31;
    if (i >= NHALF) return;

    const float4* a = (const float4*)(g_zn + (size_t)i * DDIM);
    const float4* b = (const float4*)(g_zn + (size_t)(i + NHALF) * DDIM);
    float4 a0 = a[lane], a1 = a[lane + 32];
    float4 b0 = b[lane], b1 = b[lane + 32];
    float d = a0.x*b0.x + a0.y*b0.y + a0.z*b0.z + a0.w*b0.w
            + a1.x*b1.x + a1.y*b1.y + a1.z*b1.z + a1.w*b1.w;
    #pragma unroll
    for (int o = 16; o > 0; o >>= 1) d += __shfl_xor_sync(0xffffffffu, d, o);
    if (lane == 0) atomicAdd(&g_sum_p, d * 4.0f);  // 2/T = 4
}

// ---------------------------------------------------------------------------
// Kernel 3: fused sim-tile GEMM + exp + row-sum accumulation.
// Grid (64, 64): block = 128x128 tile of sim. 256 threads, 8x8 microtiles.
// ---------------------------------------------------------------------------
#define BM 128
#define BN 128
#define BK 32

__global__ void __launch_bounds__(256) k_simexp() {
    __shared__ float As[BK][BM + 4];
    __shared__ float Bs[BK][BN + 4];

    const int rb = blockIdx.y * BM;
    const int cb = blockIdx.x * BN;
    const int tid = threadIdx.x;
    const int tx = tid & 15;        // col group
    const int ty = tid >> 4;        // row group

    float acc[8][8];
    #pragma unroll
    for (int i = 0; i < 8; ++i)
        #pragma unroll
        for (int j = 0; j < 8; ++j) acc[i][j] = 0.0f;

    for (int k0 = 0; k0 < DDIM; k0 += BK) {
        // Load 128x32 tiles of A (sim rows) and B (sim cols) — both from g_zn.
        #pragma unroll
        for (int p = 0; p < 4; ++p) {
            int r  = (tid >> 3) + p * 32;   // 0..127
            int c4 = (tid & 7);             // 0..7 -> cols c4*4..c4*4+3
            float4 a = *(const float4*)(&g_zn[(size_t)(rb + r) * DDIM + k0 + c4 * 4]);
            As[c4*4+0][r] = a.x; As[c4*4+1][r] = a.y;
            As[c4*4+2][r] = a.z; As[c4*4+3][r] = a.w;
            float4 b = *(const float4*)(&g_zn[(size_t)(cb + r) * DDIM + k0 + c4 * 4]);
            Bs[c4*4+0][r] = b.x; Bs[c4*4+1][r] = b.y;
            Bs[c4*4+2][r] = b.z; Bs[c4*4+3][r] = b.w;
        }
        __syncthreads();

        #pragma unroll
        for (int k = 0; k < BK; ++k) {
            float ra[8], rbv[8];
            #pragma unroll
            for (int i = 0; i < 8; ++i) ra[i]  = As[k][ty * 8 + i];
            #pragma unroll
            for (int j = 0; j < 8; ++j) rbv[j] = Bs[k][tx * 8 + j];
            #pragma unroll
            for (int i = 0; i < 8; ++i)
                #pragma unroll
                for (int j = 0; j < 8; ++j)
                    acc[i][j] = fmaf(ra[i], rbv[j], acc[i][j]);
        }
        __syncthreads();
    }

    // exp(sim/T) and per-row partial sums (8 rows per thread)
    float rsum[8];
    #pragma unroll
    for (int i = 0; i < 8; ++i) {
        float s = 0.0f;
        #pragma unroll
        for (int j = 0; j < 8; ++j) s += exp2f(acc[i][j] * LOG2E_X2);
        rsum[i] = s;
    }
    // Reduce across the 16 tx lanes (contiguous half-warp segments of width 16).
    #pragma unroll
    for (int i = 0; i < 8; ++i) {
        #pragma unroll
        for (int o = 8; o > 0; o >>= 1)
            rsum[i] += __shfl_down_sync(0xffffffffu, rsum[i], o, 16);
    }
    if (tx == 0) {
        #pragma unroll
        for (int i = 0; i < 8; ++i)
            atomicAdd(&g_rs[rb + ty * 8 + i], rsum[i]);
    }
}

// ---------------------------------------------------------------------------
// Kernel 4: final reduction to the scalar loss.
// ---------------------------------------------------------------------------
__global__ void __launch_bounds__(256) k_final(float* __restrict__ out) {
    __shared__ double red[256];
    double s = 0.0;
    for (int r = threadIdx.x; r < NROWS; r += 256) {
        float rs = g_rs[r];
        s += 8191.0 * (double)logf(rs)
           + (double)logf(fmaxf(rs - 1.0f, 1e-8f));
    }
    red[threadIdx.x] = s;
    __syncthreads();
    for (int o = 128; o > 0; o >>= 1) {
        if (threadIdx.x < o) red[threadIdx.x] += red[threadIdx.x + o];
        __syncthreads();
    }
    if (threadIdx.x == 0) {
        double Sd = red[0];
        double loss = (Sd - 8192.0 * (double)g_sum_p) / (8192.0 * 8192.0);
        out[0] = (float)loss;
    }
}

// ---------------------------------------------------------------------------
extern "C" void kernel_launch(void* const* d_in, const int* in_sizes, int n_in,
                              void* d_out, int out_size) {
    (void)in_sizes; (void)n_in; (void)out_size;
    const float* zi = (const float*)d_in[0];
    const float* zj = (const float*)d_in[1];
    float* out = (float*)d_out;

    k_normalize<<<1024, 256>>>(zi, zj);
    k_positives<<<512, 256>>>();
    k_simexp<<<dim3(64, 64), 256>>>();
    k_final<<<1, 256>>>(out);
}

// round 5
// speedup vs baseline: 7.8827x; 7.8827x over previous
#include <cuda_runtime.h>
#include <cuda_bf16.h>
#include <math.h>
#include <cstdint>

// NT-Xent loss, N=4096, D=256, T=0.5, EPS=1e-8.
// loss = (S_d - 2N*S_p) / (2N)^2
//   S_p = (2/T) * sum_i dot(zn_i, zn_{i+N})          (fp32)
//   S_d = sum_j [(2N-1)*log(rs_j) + log(max(rs_j-1,EPS))]
//   rs_j = sum_k exp(sim_jk/T), sim = zn@zn^T        (bf16 mma.sync HMMA)

#define NROWS 8192
#define NHALF 4096
#define DDIM  256
#define LOG2E_X2 2.8853900817779268f   // exp(2s) = 2^(s*2*log2 e)

__device__ float          g_zn [NROWS * DDIM];   // fp32 normalized (positives)
__device__ __nv_bfloat16  g_znb[NROWS * DDIM];   // bf16 normalized (GEMM)
__device__ float          g_rs [NROWS];
__device__ float          g_sum_p;
__device__ double         g_sd;

// ===================== PTX helpers ==========================================
__device__ __forceinline__ uint32_t smem_u32(const void* p) {
    uint32_t a;
    asm("{ .reg .u64 t; cvta.to.shared.u64 t, %1; cvt.u32.u64 %0, t; }" : "=r"(a) : "l"(p));
    return a;
}
#define CP_ASYNC16(sm, gp) \
    asm volatile("cp.async.cg.shared.global [%0], [%1], 16;" :: "r"(sm), "l"(gp))
#define CP_COMMIT() asm volatile("cp.async.commit_group;" ::: "memory")
#define CP_WAIT_1() asm volatile("cp.async.wait_group 1;" ::: "memory")
#define CP_WAIT_0() asm volatile("cp.async.wait_group 0;" ::: "memory")

#define LDSM_X4(r0, r1, r2, r3, addr) \
    asm volatile("ldmatrix.sync.aligned.m8n8.x4.shared.b16 {%0,%1,%2,%3}, [%4];" \
        : "=r"(r0), "=r"(r1), "=r"(r2), "=r"(r3) : "r"(addr))

#define MMA16816(d, a, b0, b1) \
    asm volatile("mma.sync.aligned.m16n8k16.row.col.f32.bf16.bf16.f32 " \
        "{%0,%1,%2,%3}, {%4,%5,%6,%7}, {%8,%9}, {%0,%1,%2,%3};" \
        : "+f"((d)[0]), "+f"((d)[1]), "+f"((d)[2]), "+f"((d)[3]) \
        : "r"((a)[0]), "r"((a)[1]), "r"((a)[2]), "r"((a)[3]), "r"(b0), "r"(b1))

__device__ __forceinline__ float ex2f(float x) {
    float y; asm("ex2.approx.f32 %0, %1;" : "=f"(y) : "f"(x)); return y;
}

// ===================== Kernel 1: normalize ==================================
__global__ void __launch_bounds__(256) k_normalize(const float* __restrict__ zi,
                                                   const float* __restrict__ zj) {
    int gtid = blockIdx.x * 256 + threadIdx.x;
    if (gtid < NROWS) g_rs[gtid] = 0.0f;
    if (gtid == 0) { g_sum_p = 0.0f; g_sd = 0.0; }

    int row  = gtid >> 5;
    int lane = threadIdx.x & 31;
    if (row >= NROWS) return;

    const float* src = (row < NHALF) ? (zi + (size_t)row * DDIM)
                                     : (zj + (size_t)(row - NHALF) * DDIM);
    float4 v0 = ((const float4*)src)[lane];
    float4 v1 = ((const float4*)src)[lane + 32];
    float s = v0.x*v0.x + v0.y*v0.y + v0.z*v0.z + v0.w*v0.w
            + v1.x*v1.x + v1.y*v1.y + v1.z*v1.z + v1.w*v1.w;
    #pragma unroll
    for (int o = 16; o > 0; o >>= 1) s += __shfl_xor_sync(0xffffffffu, s, o);

    float inv = 1.0f / fmaxf(sqrtf(s), 1e-8f);
    float4 w0 = make_float4(v0.x*inv, v0.y*inv, v0.z*inv, v0.w*inv);
    float4 w1 = make_float4(v1.x*inv, v1.y*inv, v1.z*inv, v1.w*inv);
    float4* dst = (float4*)(g_zn + (size_t)row * DDIM);
    dst[lane]      = w0;
    dst[lane + 32] = w1;

    __nv_bfloat162* db = (__nv_bfloat162*)(g_znb + (size_t)row * DDIM);
    db[lane*2+0]        = __float22bfloat162_rn(make_float2(w0.x, w0.y));
    db[lane*2+1]        = __float22bfloat162_rn(make_float2(w0.z, w0.w));
    db[64 + lane*2 + 0] = __float22bfloat162_rn(make_float2(w1.x, w1.y));
    db[64 + lane*2 + 1] = __float22bfloat162_rn(make_float2(w1.z, w1.w));
}

// ===================== Kernel 2: positives (fp32) ===========================
__global__ void __launch_bounds__(256) k_positives() {
    int gtid = blockIdx.x * 256 + threadIdx.x;
    int i    = gtid >> 5;
    int lane = threadIdx.x & 31;
    if (i >= NHALF) return;

    const float4* a = (const float4*)(g_zn + (size_t)i * DDIM);
    const float4* b = (const float4*)(g_zn + (size_t)(i + NHALF) * DDIM);
    float4 a0 = a[lane], a1 = a[lane + 32];
    float4 b0 = b[lane], b1 = b[lane + 32];
    float d = a0.x*b0.x + a0.y*b0.y + a0.z*b0.z + a0.w*b0.w
            + a1.x*b1.x + a1.y*b1.y + a1.z*b1.z + a1.w*b1.w;
    #pragma unroll
    for (int o = 16; o > 0; o >>= 1) d += __shfl_xor_sync(0xffffffffu, d, o);
    if (lane == 0) atomicAdd(&g_sum_p, d * 4.0f);  // 2/T = 4
}

// ===================== Kernel 3: HMMA sim-GEMM + exp + rowsum ===============
// 128x128 sim tile per CTA; 8 warps (2 x 4), warp tile 64x32.
// K=256 in 4 stages of BK=64; cp.async double buffer; SW128 ldmatrix layout.
#define BM 128
#define BN 128
#define BK 64
#define NSTAGE 4

// SMEM (dynamic): A[2][128][128B] @0 (32KB), B[2][128][128B] @32768 (32KB),
// srow[128] floats @65536.
#define SMA      0
#define SMB      32768
#define SMROW    65536
#define SM_TOTAL (65536 + 512)
#define STAGE_BYTES 16384

__global__ void __launch_bounds__(256) k_simexp() {
    extern __shared__ char smem[];
    float* srow = (float*)(smem + SMROW);
    const uint32_t sb = smem_u32(smem);
    const int tid  = threadIdx.x;
    const int wid  = tid >> 5;
    const int lane = tid & 31;
    const int wr   = wid >> 2;     // warp row 0..1  (64 m-rows each)
    const int wc   = wid & 3;      // warp col 0..3  (32 n-cols each)
    const int rb   = blockIdx.y * BM;
    const int cb   = blockIdx.x * BN;

    if (tid < BM) srow[tid] = 0.0f;

    const __nv_bfloat16* Agp = g_znb + (size_t)rb * DDIM;
    const __nv_bfloat16* Bgp = g_znb + (size_t)cb * DDIM;

    // ldmatrix per-lane constants.
    // A: row = wr*64 + mt*16 + (lane&15); chunk = ks*2 + (lane>>4)
    // B: row = wc*32 + bt*16 + (lane&7) + ((lane>>4)<<3); chunk = ks*2 + ((lane>>3)&1)
    const uint32_t rowAb = (uint32_t)(wr * 64 + (lane & 15)) * 128u;
    const uint32_t rowBb = (uint32_t)(wc * 32 + (lane & 7) + ((lane >> 4) << 3)) * 128u;
    const uint32_t swzA0 = (uint32_t)(lane >> 4);        // chunk low bits from lane
    const uint32_t swzB0 = (uint32_t)((lane >> 3) & 1);
    const uint32_t lxor  = (uint32_t)(lane & 7);

    float acc[4][4][4];
    #pragma unroll
    for (int mt = 0; mt < 4; ++mt)
        #pragma unroll
        for (int nt = 0; nt < 4; ++nt)
            #pragma unroll
            for (int e = 0; e < 4; ++e) acc[mt][nt][e] = 0.0f;

    // ---- stage loader: 1024 16B-chunks each for A and B; 4 per thread each
    auto load_stage = [&](int s, int buf) {
        const int k0 = s * BK;
        #pragma unroll
        for (int t = 0; t < 4; ++t) {
            int idx = tid + t * 256;           // 0..1023
            int r   = idx >> 3;                // 0..127
            int c   = idx & 7;                 // 16B chunk in row
            uint32_t so = (uint32_t)r * 128u + (uint32_t)((c ^ (r & 7)) << 4);
            CP_ASYNC16(sb + SMA + buf * STAGE_BYTES + so, Agp + (size_t)r * DDIM + k0 + c * 8);
            CP_ASYNC16(sb + SMB + buf * STAGE_BYTES + so, Bgp + (size_t)r * DDIM + k0 + c * 8);
        }
        CP_COMMIT();
    };

    load_stage(0, 0);

    for (int s = 0; s < NSTAGE; ++s) {
        const int buf = s & 1;
        if (s + 1 < NSTAGE) { load_stage(s + 1, (s + 1) & 1); CP_WAIT_1(); }
        else                { CP_WAIT_0(); }
        __syncthreads();

        const uint32_t abase = sb + SMA + buf * STAGE_BYTES;
        const uint32_t bbase = sb + SMB + buf * STAGE_BYTES;

        #pragma unroll
        for (int ks = 0; ks < 4; ++ks) {
            uint32_t a[4][4];
            const uint32_t cA = (uint32_t)(ks * 2) + swzA0;
            const uint32_t aoff = abase + rowAb + ((cA ^ lxor) << 4);
            #pragma unroll
            for (int mt = 0; mt < 4; ++mt)
                LDSM_X4(a[mt][0], a[mt][1], a[mt][2], a[mt][3], aoff + mt * 2048);

            uint32_t b[2][4];
            const uint32_t cB = (uint32_t)(ks * 2) + swzB0;
            const uint32_t boff = bbase + rowBb + ((cB ^ lxor) << 4);
            #pragma unroll
            for (int bt = 0; bt < 2; ++bt)
                LDSM_X4(b[bt][0], b[bt][1], b[bt][2], b[bt][3], boff + bt * 2048);

            #pragma unroll
            for (int mt = 0; mt < 4; ++mt)
                #pragma unroll
                for (int nt = 0; nt < 4; ++nt)
                    MMA16816(acc[mt][nt], a[mt],
                             b[nt >> 1][(nt & 1) * 2], b[nt >> 1][(nt & 1) * 2 + 1]);
        }
        __syncthreads();
    }

    // ---- epilogue: exp(2*sim) row sums --------------------------------------
    #pragma unroll
    for (int mt = 0; mt < 4; ++mt) {
        float slow = 0.0f, shigh = 0.0f;
        #pragma unroll
        for (int nt = 0; nt < 4; ++nt) {
            slow  += ex2f(acc[mt][nt][0] * LOG2E_X2) + ex2f(acc[mt][nt][1] * LOG2E_X2);
            shigh += ex2f(acc[mt][nt][2] * LOG2E_X2) + ex2f(acc[mt][nt][3] * LOG2E_X2);
        }
        // reduce across the 4 lanes that hold the same row (l%4 = 0..3)
        #pragma unroll
        for (int o = 1; o < 4; o <<= 1) {
            slow  += __shfl_xor_sync(0xffffffffu, slow,  o);
            shigh += __shfl_xor_sync(0xffffffffu, shigh, o);
        }
        if ((lane & 3) == 0) {
            int r = wr * 64 + mt * 16 + (lane >> 2);
            atomicAdd(&srow[r],     slow);
            atomicAdd(&srow[r + 8], shigh);
        }
    }
    __syncthreads();
    if (tid < BM) atomicAdd(&g_rs[rb + tid], srow[tid]);
}

// ===================== Kernel 4a: S_d partial sums ==========================
__global__ void __launch_bounds__(256) k_sd() {
    __shared__ double red[256];
    double s = 0.0;
    for (int r = blockIdx.x * 256 + threadIdx.x; r < NROWS; r += gridDim.x * 256) {
        float rs = g_rs[r];
        s += 8191.0 * (double)logf(rs) + (double)logf(fmaxf(rs - 1.0f, 1e-8f));
    }
    red[threadIdx.x] = s;
    __syncthreads();
    for (int o = 128; o > 0; o >>= 1) {
        if (threadIdx.x < o) red[threadIdx.x] += red[threadIdx.x + o];
        __syncthreads();
    }
    if (threadIdx.x == 0) atomicAdd(&g_sd, red[0]);
}

// ===================== Kernel 4b: write loss ================================
__global__ void k_write(float* __restrict__ out) {
    double loss = (g_sd - 8192.0 * (double)g_sum_p) / (8192.0 * 8192.0);
    out[0] = (float)loss;
}

// ===================== launch ===============================================
extern "C" void kernel_launch(void* const* d_in, const int* in_sizes, int n_in,
                              void* d_out, int out_size) {
    (void)in_sizes; (void)n_in; (void)out_size;
    const float* zi = (const float*)d_in[0];
    const float* zj = (const float*)d_in[1];
    float* out = (float*)d_out;

    cudaFuncSetAttribute(k_simexp, cudaFuncAttributeMaxDynamicSharedMemorySize, SM_TOTAL);

    k_normalize<<<1024, 256>>>(zi, zj);
    k_positives<<<512, 256>>>();
    k_simexp<<<dim3(NROWS / BN, NROWS / BM), 256, SM_TOTAL>>>();
    k_sd<<<32, 256>>>();
    k_write<<<1, 1>>>(out);
}

// round 6
// speedup vs baseline: 11.0338x; 1.3997x over previous
#include <cuda_runtime.h>
#include <cuda_bf16.h>
#include <math.h>
#include <cstdint>

// NT-Xent loss, N=4096, D=256, T=0.5, EPS=1e-8.
// loss = (S_d - 2N*S_p) / (2N)^2
//   S_p = (2/T) * sum_i dot(zn_i, zn_{i+N})          (fp32)
//   S_d = sum_j [(2N-1)*log(rs_j) + log(max(rs_j-1,EPS))]
//   rs_j = sum_k exp(sim_jk/T), sim = zn@zn^T        (bf16 HMMA, symmetric:
//   only lower-triangle tiles computed; off-diag tiles emit row AND col sums)

#define NROWS 8192
#define NHALF 4096
#define DDIM  256
#define LOG2E_X2 2.8853900817779268f   // exp(2s) = 2^(s*2*log2 e)

__device__ float          g_zn [NROWS * DDIM];   // fp32 normalized (positives)
__device__ __nv_bfloat16  g_znb[NROWS * DDIM];   // bf16 normalized (GEMM)
__device__ float          g_rs [NROWS];
__device__ float          g_sum_p;
__device__ double         g_sd;

// ===================== PTX helpers ==========================================
__device__ __forceinline__ uint32_t smem_u32(const void* p) {
    uint32_t a;
    asm("{ .reg .u64 t; cvta.to.shared.u64 t, %1; cvt.u32.u64 %0, t; }" : "=r"(a) : "l"(p));
    return a;
}
#define CP_ASYNC16(sm, gp) \
    asm volatile("cp.async.cg.shared.global [%0], [%1], 16;" :: "r"(sm), "l"(gp))
#define CP_COMMIT() asm volatile("cp.async.commit_group;" ::: "memory")
#define CP_WAIT_1() asm volatile("cp.async.wait_group 1;" ::: "memory")
#define CP_WAIT_0() asm volatile("cp.async.wait_group 0;" ::: "memory")

#define LDSM_X4(r0, r1, r2, r3, addr) \
    asm volatile("ldmatrix.sync.aligned.m8n8.x4.shared.b16 {%0,%1,%2,%3}, [%4];" \
        : "=r"(r0), "=r"(r1), "=r"(r2), "=r"(r3) : "r"(addr))

#define MMA16816(d, a, b0, b1) \
    asm volatile("mma.sync.aligned.m16n8k16.row.col.f32.bf16.bf16.f32 " \
        "{%0,%1,%2,%3}, {%4,%5,%6,%7}, {%8,%9}, {%0,%1,%2,%3};" \
        : "+f"((d)[0]), "+f"((d)[1]), "+f"((d)[2]), "+f"((d)[3]) \
        : "r"((a)[0]), "r"((a)[1]), "r"((a)[2]), "r"((a)[3]), "r"(b0), "r"(b1))

__device__ __forceinline__ float ex2f(float x) {
    float y; asm("ex2.approx.f32 %0, %1;" : "=f"(y) : "f"(x)); return y;
}

// ===================== Kernel 1: normalize ==================================
__global__ void __launch_bounds__(256) k_normalize(const float* __restrict__ zi,
                                                   const float* __restrict__ zj) {
    int gtid = blockIdx.x * 256 + threadIdx.x;
    if (gtid < NROWS) g_rs[gtid] = 0.0f;
    if (gtid == 0) { g_sum_p = 0.0f; g_sd = 0.0; }

    int row  = gtid >> 5;
    int lane = threadIdx.x & 31;
    if (row >= NROWS) return;

    const float* src = (row < NHALF) ? (zi + (size_t)row * DDIM)
                                     : (zj + (size_t)(row - NHALF) * DDIM);
    float4 v0 = ((const float4*)src)[lane];
    float4 v1 = ((const float4*)src)[lane + 32];
    float s = v0.x*v0.x + v0.y*v0.y + v0.z*v0.z + v0.w*v0.w
            + v1.x*v1.x + v1.y*v1.y + v1.z*v1.z + v1.w*v1.w;
    #pragma unroll
    for (int o = 16; o > 0; o >>= 1) s += __shfl_xor_sync(0xffffffffu, s, o);

    float inv = 1.0f / fmaxf(sqrtf(s), 1e-8f);
    float4 w0 = make_float4(v0.x*inv, v0.y*inv, v0.z*inv, v0.w*inv);
    float4 w1 = make_float4(v1.x*inv, v1.y*inv, v1.z*inv, v1.w*inv);
    float4* dst = (float4*)(g_zn + (size_t)row * DDIM);
    dst[lane]      = w0;
    dst[lane + 32] = w1;

    __nv_bfloat162* db = (__nv_bfloat162*)(g_znb + (size_t)row * DDIM);
    db[lane*2+0]        = __float22bfloat162_rn(make_float2(w0.x, w0.y));
    db[lane*2+1]        = __float22bfloat162_rn(make_float2(w0.z, w0.w));
    db[64 + lane*2 + 0] = __float22bfloat162_rn(make_float2(w1.x, w1.y));
    db[64 + lane*2 + 1] = __float22bfloat162_rn(make_float2(w1.z, w1.w));
}

// ===================== Kernel 2: positives (fp32) ===========================
__global__ void __launch_bounds__(256) k_positives() {
    int gtid = blockIdx.x * 256 + threadIdx.x;
    int i    = gtid >> 5;
    int lane = threadIdx.x & 31;
    if (i >= NHALF) return;

    const float4* a = (const float4*)(g_zn + (size_t)i * DDIM);
    const float4* b = (const float4*)(g_zn + (size_t)(i + NHALF) * DDIM);
    float4 a0 = a[lane], a1 = a[lane + 32];
    float4 b0 = b[lane], b1 = b[lane + 32];
    float d = a0.x*b0.x + a0.y*b0.y + a0.z*b0.z + a0.w*b0.w
            + a1.x*b1.x + a1.y*b1.y + a1.z*b1.z + a1.w*b1.w;
    #pragma unroll
    for (int o = 16; o > 0; o >>= 1) d += __shfl_xor_sync(0xffffffffu, d, o);
    if (lane == 0) atomicAdd(&g_sum_p, d * 4.0f);  // 2/T = 4
}

// ===================== Kernel 3: symmetric HMMA sim-GEMM + exp + sums =======
// Lower-triangle tiles only: 64*65/2 = 2080 CTAs. Tile (bi, bj), bj <= bi.
// 128x128 per CTA; 8 warps (2x4), warp tile 64x32; K=256, 4 stages of BK=64.
#define BM 128
#define BN 128
#define BK 64
#define NSTAGE 4
#define NTB (NROWS / BM)                 // 64 tile blocks
#define NTILES (NTB * (NTB + 1) / 2)     // 2080

// SMEM: A[2][16KB] @0, B[2][16KB] @32768, srow[128] @65536, scol[128] @66048
#define SMA      0
#define SMB      32768
#define SMROW    65536
#define SMCOL    66048
#define SM_TOTAL (66048 + 512)
#define STAGE_BYTES 16384

__global__ void __launch_bounds__(256) k_simexp() {
    extern __shared__ char smem[];
    float* srow = (float*)(smem + SMROW);
    float* scol = (float*)(smem + SMCOL);
    const uint32_t sb = smem_u32(smem);
    const int tid  = threadIdx.x;
    const int wid  = tid >> 5;
    const int lane = tid & 31;
    const int wr   = wid >> 2;     // warp row 0..1
    const int wc   = wid & 3;      // warp col 0..3

    // decode lower-triangle tile index: t = bi*(bi+1)/2 + bj, bj <= bi
    int t  = blockIdx.x;
    int bi = (int)((sqrtf(8.0f * (float)t + 1.0f) - 1.0f) * 0.5f);
    while ((bi + 1) * (bi + 2) / 2 <= t) ++bi;
    while (bi * (bi + 1) / 2 > t)        --bi;
    int bj = t - bi * (bi + 1) / 2;
    const int rb   = bi * BM;
    const int cb   = bj * BN;
    const bool diag = (bi == bj);

    if (tid < BM) { srow[tid] = 0.0f; scol[tid] = 0.0f; }

    const __nv_bfloat16* Agp = g_znb + (size_t)rb * DDIM;
    const __nv_bfloat16* Bgp = g_znb + (size_t)cb * DDIM;

    const uint32_t rowAb = (uint32_t)(wr * 64 + (lane & 15)) * 128u;
    const uint32_t rowBb = (uint32_t)(wc * 32 + (lane & 7) + ((lane >> 4) << 3)) * 128u;
    const uint32_t swzA0 = (uint32_t)(lane >> 4);
    const uint32_t swzB0 = (uint32_t)((lane >> 3) & 1);
    const uint32_t lxor  = (uint32_t)(lane & 7);

    float acc[4][4][4];
    #pragma unroll
    for (int mt = 0; mt < 4; ++mt)
        #pragma unroll
        for (int nt = 0; nt < 4; ++nt)
            #pragma unroll
            for (int e = 0; e < 4; ++e) acc[mt][nt][e] = 0.0f;

    auto load_stage = [&](int s, int buf) {
        const int k0 = s * BK;
        #pragma unroll
        for (int tt = 0; tt < 4; ++tt) {
            int idx = tid + tt * 256;
            int r   = idx >> 3;
            int c   = idx & 7;
            uint32_t so = (uint32_t)r * 128u + (uint32_t)((c ^ (r & 7)) << 4);
            CP_ASYNC16(sb + SMA + buf * STAGE_BYTES + so, Agp + (size_t)r * DDIM + k0 + c * 8);
            if (!diag)
                CP_ASYNC16(sb + SMB + buf * STAGE_BYTES + so, Bgp + (size_t)r * DDIM + k0 + c * 8);
        }
        CP_COMMIT();
    };

    load_stage(0, 0);

    for (int s = 0; s < NSTAGE; ++s) {
        const int buf = s & 1;
        if (s + 1 < NSTAGE) { load_stage(s + 1, (s + 1) & 1); CP_WAIT_1(); }
        else                { CP_WAIT_0(); }
        __syncthreads();

        const uint32_t abase = sb + SMA + buf * STAGE_BYTES;
        const uint32_t bbase = diag ? abase : (sb + SMB + buf * STAGE_BYTES);

        #pragma unroll
        for (int ks = 0; ks < 4; ++ks) {
            uint32_t a[4][4];
            const uint32_t cA = (uint32_t)(ks * 2) + swzA0;
            const uint32_t aoff = abase + rowAb + ((cA ^ lxor) << 4);
            #pragma unroll
            for (int mt = 0; mt < 4; ++mt)
                LDSM_X4(a[mt][0], a[mt][1], a[mt][2], a[mt][3], aoff + mt * 2048);

            uint32_t b[2][4];
            const uint32_t cB = (uint32_t)(ks * 2) + swzB0;
            const uint32_t boff = bbase + rowBb + ((cB ^ lxor) << 4);
            #pragma unroll
            for (int bt = 0; bt < 2; ++bt)
                LDSM_X4(b[bt][0], b[bt][1], b[bt][2], b[bt][3], boff + bt * 2048);

            #pragma unroll
            for (int mt = 0; mt < 4; ++mt)
                #pragma unroll
                for (int nt = 0; nt < 4; ++nt)
                    MMA16816(acc[mt][nt], a[mt],
                             b[nt >> 1][(nt & 1) * 2], b[nt >> 1][(nt & 1) * 2 + 1]);
        }
        __syncthreads();
    }

    // ---- epilogue: exp(2*sim); rows always; cols when off-diagonal ---------
    // fragment: row = wr*64 + mt*16 + (lane>>2) (+8 for e2/e3)
    //           col = wc*32 + nt*8 + (lane&3)*2 (+1 for e1/e3)
    float csum0[4] = {0,0,0,0}, csum1[4] = {0,0,0,0};
    #pragma unroll
    for (int mt = 0; mt < 4; ++mt) {
        float slow = 0.0f, shigh = 0.0f;
        #pragma unroll
        for (int nt = 0; nt < 4; ++nt) {
            float e0 = ex2f(acc[mt][nt][0] * LOG2E_X2);
            float e1 = ex2f(acc[mt][nt][1] * LOG2E_X2);
            float e2 = ex2f(acc[mt][nt][2] * LOG2E_X2);
            float e3 = ex2f(acc[mt][nt][3] * LOG2E_X2);
            slow  += e0 + e1;
            shigh += e2 + e3;
            csum0[nt] += e0 + e2;
            csum1[nt] += e1 + e3;
        }
        #pragma unroll
        for (int o = 1; o < 4; o <<= 1) {
            slow  += __shfl_xor_sync(0xffffffffu, slow,  o);
            shigh += __shfl_xor_sync(0xffffffffu, shigh, o);
        }
        if ((lane & 3) == 0) {
            int r = wr * 64 + mt * 16 + (lane >> 2);
            atomicAdd(&srow[r],     slow);
            atomicAdd(&srow[r + 8], shigh);
        }
    }
    if (!diag) {
        #pragma unroll
        for (int nt = 0; nt < 4; ++nt) {
            #pragma unroll
            for (int o = 4; o < 32; o <<= 1) {
                csum0[nt] += __shfl_xor_sync(0xffffffffu, csum0[nt], o);
                csum1[nt] += __shfl_xor_sync(0xffffffffu, csum1[nt], o);
            }
            if (lane < 4) {
                int c = wc * 32 + nt * 8 + lane * 2;
                atomicAdd(&scol[c],     csum0[nt]);
                atomicAdd(&scol[c + 1], csum1[nt]);
            }
        }
    }
    __syncthreads();
    if (tid < BM) {
        atomicAdd(&g_rs[rb + tid], srow[tid]);
        if (!diag) atomicAdd(&g_rs[cb + tid], scol[tid]);
    }
}

// ===================== Kernel 4a: S_d partial sums ==========================
__global__ void __launch_bounds__(256) k_sd() {
    __shared__ double red[256];
    double s = 0.0;
    for (int r = blockIdx.x * 256 + threadIdx.x; r < NROWS; r += gridDim.x * 256) {
        float rs = g_rs[r];
        s += 8191.0 * (double)logf(rs) + (double)logf(fmaxf(rs - 1.0f, 1e-8f));
    }
    red[threadIdx.x] = s;
    __syncthreads();
    for (int o = 128; o > 0; o >>= 1) {
        if (threadIdx.x < o) red[threadIdx.x] += red[threadIdx.x + o];
        __syncthreads();
    }
    if (threadIdx.x == 0) atomicAdd(&g_sd, red[0]);
}

// ===================== Kernel 4b: write loss ================================
__global__ void k_write(float* __restrict__ out) {
    double loss = (g_sd - 8192.0 * (double)g_sum_p) / (8192.0 * 8192.0);
    out[0] = (float)loss;
}

// ===================== launch ===============================================
extern "C" void kernel_launch(void* const* d_in, const int* in_sizes, int n_in,
                              void* d_out, int out_size) {
    (void)in_sizes; (void)n_in; (void)out_size;
    const float* zi = (const float*)d_in[0];
    const float* zj = (const float*)d_in[1];
    float* out = (float*)d_out;

    cudaFuncSetAttribute(k_simexp, cudaFuncAttributeMaxDynamicSharedMemorySize, SM_TOTAL);

    k_normalize<<<1024, 256>>>(zi, zj);
    k_positives<<<512, 256>>>();
    k_simexp<<<NTILES, 256, SM_TOTAL>>>();
    k_sd<<<32, 256>>>();
    k_write<<<1, 1>>>(out);
}